// round 1
// baseline (speedup 1.0000x reference)
#include <cuda_runtime.h>
#include <cstddef>

#define NNODES 50000
#define HID    128
#define NGRAPH 256

// ---- scratch (device globals; no allocation allowed) ----
__device__ float g_h[(size_t)NNODES * HID];   // 25.6 MB
__device__ float g_t[(size_t)NNODES * HID];   // 25.6 MB
__device__ float g_dinv[NNODES];
__device__ float g_pool[NGRAPH * HID];
__device__ float g_cnt[NGRAPH];
__device__ float g_Wt[HID * HID];

// ---------------- small kernels ----------------
__global__ void k_deg_init(float* deg, int n) {
    int i = blockIdx.x * blockDim.x + threadIdx.x;
    if (i < n) deg[i] = 1.0f;   // self-loop weight
}

__global__ void k_deg_acc(const int* __restrict__ dst, const float* __restrict__ ew,
                          float* deg, int E) {
    int e = blockIdx.x * blockDim.x + threadIdx.x;
    if (e < E) atomicAdd(&deg[dst[e]], ew[e]);
}

__global__ void k_rsqrt(float* d, int n) {
    int i = blockIdx.x * blockDim.x + threadIdx.x;
    if (i < n) d[i] = rsqrtf(d[i]);
}

// Wt[k][j] = W[j][k]  (128x128, tiny)
__global__ void k_transpose(const float* __restrict__ W, float* __restrict__ Wt) {
    int idx = blockIdx.x * blockDim.x + threadIdx.x;  // 0..16383
    int k = idx >> 7, j = idx & 127;
    Wt[idx] = W[j * HID + k];
}

// ---------------- GEMM: O[n,128] = X[n,128] @ W^T (Wt is k-major) ----------------
__global__ void __launch_bounds__(256)
k_gemm(const float* __restrict__ X, const float* __restrict__ Wt,
       float* __restrict__ O, int nrows) {
    extern __shared__ float sm[];
    float* Xs = sm;                  // [128][132]  row-major, padded
    float* Ws = sm + 128 * 132;      // [128][128]  k-major (j contiguous)
    int tid = threadIdx.x;
    int tx = tid & 15, ty = tid >> 4;
    int row0 = blockIdx.x * 128;

#pragma unroll
    for (int i = 0; i < 16; i++) {
        int idx = i * 256 + tid;      // 0..4095 (float4 index)
        int r = idx >> 5, k4 = idx & 31;
        int grow = row0 + r;
        float4 v = make_float4(0.f, 0.f, 0.f, 0.f);
        if (grow < nrows) v = ((const float4*)(X + (size_t)grow * HID))[k4];
        *(float4*)(Xs + r * 132 + k4 * 4) = v;
        ((float4*)Ws)[idx] = ((const float4*)Wt)[idx];
    }
    __syncthreads();

    float acc[8][8];
#pragma unroll
    for (int i = 0; i < 8; i++)
#pragma unroll
        for (int j = 0; j < 8; j++) acc[i][j] = 0.f;

#pragma unroll 4
    for (int k = 0; k < 128; k++) {
        float a[8];
#pragma unroll
        for (int i = 0; i < 8; i++) a[i] = Xs[(ty * 8 + i) * 132 + k];
        float4 b0 = *(const float4*)(Ws + k * 128 + tx * 8);
        float4 b1 = *(const float4*)(Ws + k * 128 + tx * 8 + 4);
        float b[8] = {b0.x, b0.y, b0.z, b0.w, b1.x, b1.y, b1.z, b1.w};
#pragma unroll
        for (int i = 0; i < 8; i++)
#pragma unroll
            for (int j = 0; j < 8; j++) acc[i][j] += a[i] * b[j];
    }

#pragma unroll
    for (int i = 0; i < 8; i++) {
        int grow = row0 + ty * 8 + i;
        if (grow < nrows) {
            float4 o0 = make_float4(acc[i][0], acc[i][1], acc[i][2], acc[i][3]);
            float4 o1 = make_float4(acc[i][4], acc[i][5], acc[i][6], acc[i][7]);
            *(float4*)(O + (size_t)grow * HID + tx * 8) = o0;
            *(float4*)(O + (size_t)grow * HID + tx * 8 + 4) = o1;
        }
    }
}

// out[i][:] = h[i][:] * dinv[i]^2   (self-loop contribution, also zero-inits accumulator)
__global__ void k_selfinit(const float* __restrict__ h, const float* __restrict__ dinv,
                           float* __restrict__ out, int n32) {
    int i = blockIdx.x * blockDim.x + threadIdx.x;
    if (i >= n32) return;
    float di = dinv[i >> 5];
    float c = di * di;
    float4 v = ((const float4*)h)[i];
    v.x *= c; v.y *= c; v.z *= c; v.w *= c;
    ((float4*)out)[i] = v;
}

// One warp per edge: out[dst] += h[src] * (dinv[src]*w*dinv[dst])
__global__ void k_agg(const float* __restrict__ h, const int* __restrict__ src,
                      const int* __restrict__ dst, const float* __restrict__ ew,
                      const float* __restrict__ dinv, float* __restrict__ out, int E) {
    int gt = blockIdx.x * blockDim.x + threadIdx.x;
    int e = gt >> 5, lane = gt & 31;
    if (e >= E) return;
    int s = src[e], d = dst[e];
    float c = dinv[s] * ew[e] * dinv[d];
    float4 v = ((const float4*)(h + (size_t)s * HID))[lane];
    float* p = out + (size_t)d * HID + lane * 4;
    asm volatile("red.global.add.v4.f32 [%0], {%1, %2, %3, %4};"
                 :: "l"(p), "f"(v.x * c), "f"(v.y * c), "f"(v.z * c), "f"(v.w * c)
                 : "memory");
}

__global__ void k_biasrelu(const float* __restrict__ in, const float* __restrict__ b,
                           float* __restrict__ out, int n32) {
    int i = blockIdx.x * blockDim.x + threadIdx.x;
    if (i >= n32) return;
    float4 bv = ((const float4*)b)[i & 31];
    float4 v = ((const float4*)in)[i];
    v.x = fmaxf(v.x + bv.x, 0.f);
    v.y = fmaxf(v.y + bv.y, 0.f);
    v.z = fmaxf(v.z + bv.z, 0.f);
    v.w = fmaxf(v.w + bv.w, 0.f);
    ((float4*)out)[i] = v;
}

__global__ void k_poolzero() {
    int i = blockIdx.x * blockDim.x + threadIdx.x;
    if (i < NGRAPH * HID) g_pool[i] = 0.f;
    if (i < NGRAPH) g_cnt[i] = 0.f;
}

__global__ void k_pool(const float* __restrict__ a, const int* __restrict__ batch, int n) {
    int gt = blockIdx.x * blockDim.x + threadIdx.x;
    int node = gt >> 5, lane = gt & 31;
    if (node >= n) return;
    int b = batch[node];
    float4 v = ((const float4*)(a + (size_t)node * HID))[lane];
    float* p = g_pool + b * HID + lane * 4;
    asm volatile("red.global.add.v4.f32 [%0], {%1, %2, %3, %4};"
                 :: "l"(p), "f"(v.x), "f"(v.y), "f"(v.z), "f"(v.w)
                 : "memory");
    if (lane == 0) atomicAdd(&g_cnt[b], 1.0f);
}

// per-graph: z = relu(pooled @ fW1^T + fb1); out = z @ fW2^T + fb2
__global__ void k_mlp(const float* __restrict__ fW1, const float* __restrict__ fb1,
                      const float* __restrict__ fW2, const float* __restrict__ fb2,
                      float* __restrict__ out) {
    __shared__ float p[128];
    __shared__ float z[128];
    int g = blockIdx.x, t = threadIdx.x;
    float cnt = fmaxf(g_cnt[g], 1.0f);
    p[t] = g_pool[g * HID + t] / cnt;
    __syncthreads();
    float acc = fb1[t];
    const float* wr = fW1 + t * HID;
#pragma unroll 4
    for (int k = 0; k < HID; k++) acc += p[k] * wr[k];
    z[t] = fmaxf(acc, 0.f) * fW2[t];
    __syncthreads();
    if (t < 32) {
        float s = z[t] + z[t + 32] + z[t + 64] + z[t + 96];
#pragma unroll
        for (int o = 16; o; o >>= 1) s += __shfl_down_sync(0xffffffffu, s, o);
        if (t == 0) out[g] = s + fb2[0];
    }
}

// ---------------- launch ----------------
extern "C" void kernel_launch(void* const* d_in, const int* in_sizes, int n_in,
                              void* d_out, int out_size) {
    const float* x     = (const float*)d_in[0];     // [N,128]
    const int*   eidx  = (const int*)d_in[1];       // [2,E]
    const float* eattr = (const float*)d_in[2];     // [E]
    const int*   batch = (const int*)d_in[3];       // [N]
    const float* W1    = (const float*)d_in[4];
    const float* b1    = (const float*)d_in[5];
    const float* W2    = (const float*)d_in[6];
    const float* b2    = (const float*)d_in[7];
    const float* fW1   = (const float*)d_in[8];
    const float* fb1   = (const float*)d_in[9];
    const float* fW2   = (const float*)d_in[10];
    const float* fb2   = (const float*)d_in[11];
    float* out = (float*)d_out;

    int N = in_sizes[0] / HID;
    int E = in_sizes[1] / 2;
    const int* src = eidx;
    const int* dst = eidx + E;

    float *p_h, *p_t, *p_dinv, *p_Wt;
    cudaGetSymbolAddress((void**)&p_h, g_h);
    cudaGetSymbolAddress((void**)&p_t, g_t);
    cudaGetSymbolAddress((void**)&p_dinv, g_dinv);
    cudaGetSymbolAddress((void**)&p_Wt, g_Wt);

    const int T = 256;
    int n32 = N * 32;                       // float4 count over node features
    int gemm_blocks = (N + 127) / 128;
    int agg_blocks = (int)(((long long)E * 32 + T - 1) / T);
    size_t gemm_smem = (128 * 132 + 128 * 128) * sizeof(float);
    cudaFuncSetAttribute(k_gemm, cudaFuncAttributeMaxDynamicSharedMemorySize,
                         (int)gemm_smem);

    // degree + dinv
    k_deg_init<<<(N + T - 1) / T, T>>>(p_dinv, N);
    k_deg_acc<<<(E + T - 1) / T, T>>>(dst, eattr, p_dinv, E);
    k_rsqrt<<<(N + T - 1) / T, T>>>(p_dinv, N);

    // layer 1: h = x @ W1^T ; agg ; relu(+b1)
    k_transpose<<<64, T>>>(W1, p_Wt);
    k_gemm<<<gemm_blocks, T, gemm_smem>>>(x, p_Wt, p_h, N);
    k_selfinit<<<(n32 + T - 1) / T, T>>>(p_h, p_dinv, p_t, n32);
    k_agg<<<agg_blocks, T>>>(p_h, src, dst, eattr, p_dinv, p_t, E);
    k_biasrelu<<<(n32 + T - 1) / T, T>>>(p_t, b1, p_h, n32);   // a1 -> g_h

    // layer 2: h2 = a1 @ W2^T ; agg ; relu(+b2)
    k_transpose<<<64, T>>>(W2, p_Wt);
    k_gemm<<<gemm_blocks, T, gemm_smem>>>(p_h, p_Wt, p_t, N);  // h2 -> g_t
    k_selfinit<<<(n32 + T - 1) / T, T>>>(p_t, p_dinv, p_h, n32);
    k_agg<<<agg_blocks, T>>>(p_t, src, dst, eattr, p_dinv, p_h, E);
    k_biasrelu<<<(n32 + T - 1) / T, T>>>(p_h, b2, p_h, n32);   // a2 in place in g_h

    // mean pool + MLP head
    k_poolzero<<<(NGRAPH * HID + T - 1) / T, T>>>();
    k_pool<<<(n32 + T - 1) / T, T>>>(p_h, batch, N);
    k_mlp<<<NGRAPH, HID>>>(fW1, fb1, fW2, fb2, out);
}

// round 5
// speedup vs baseline: 1.2818x; 1.2818x over previous
#include <cuda_runtime.h>
#include <cstddef>

#define NNODES 50000
#define NEDGES 500000
#define HID    128
#define NGRAPH 256

// ---- scratch (device globals; no allocation allowed) ----
__device__ float g_h[(size_t)NNODES * HID];   // 25.6 MB
__device__ float g_t[(size_t)NNODES * HID];   // 25.6 MB
__device__ float g_deg[NNODES];               // weighted degree -> dinv
__device__ int   g_hist[NNODES];              // in-degree counts
__device__ int   g_rowptr[NNODES + 1];
__device__ int   g_cursor[NNODES];
__device__ int   g_bsum[64];
__device__ int   g_bpre[64];
__device__ int   g_csrc[NEDGES];
__device__ float g_cw[NEDGES];

// ---------------- CSR build ----------------
__global__ void k_init_nodes(float* deg, int* hist, int n) {
    int i = blockIdx.x * blockDim.x + threadIdx.x;
    if (i < n) { deg[i] = 1.0f; hist[i] = 0; }   // self-loop weight 1
}

__global__ void k_edge_hist(const int* __restrict__ dst, const float* __restrict__ ew,
                            float* deg, int* hist, int E) {
    int e = blockIdx.x * blockDim.x + threadIdx.x;
    if (e < E) {
        int d = dst[e];
        atomicAdd(&deg[d], ew[e]);
        atomicAdd(&hist[d], 1);
    }
}

__global__ void k_rsqrt(float* d, int n) {
    int i = blockIdx.x * blockDim.x + threadIdx.x;
    if (i < n) d[i] = rsqrtf(d[i]);
}

// per-block inclusive scan of hist (1024 elems/block) -> rowptr[1+i] (partial), bsum
__global__ void __launch_bounds__(1024) k_scan1(const int* __restrict__ hist,
                                                int* rowptr, int* bsum, int n) {
    __shared__ int s[1024];
    int t = threadIdx.x;
    int idx = blockIdx.x * 1024 + t;
    int v = (idx < n) ? hist[idx] : 0;
    s[t] = v;
    __syncthreads();
#pragma unroll
    for (int o = 1; o < 1024; o <<= 1) {
        int add = (t >= o) ? s[t - o] : 0;
        __syncthreads();
        s[t] += add;
        __syncthreads();
    }
    if (idx < n) rowptr[idx + 1] = s[t];
    if (t == 1023) bsum[blockIdx.x] = s[t];
}

__global__ void k_scan2(const int* bsum, int* bpre, int nb) {
    if (threadIdx.x == 0) {
        int run = 0;
        for (int b = 0; b < nb; b++) { bpre[b] = run; run += bsum[b]; }
    }
}

__global__ void __launch_bounds__(1024) k_scan3(int* rowptr, int* cursor,
                                                const int* bpre, int n) {
    int idx = blockIdx.x * 1024 + threadIdx.x;
    if (idx >= n) return;
    int val = rowptr[idx + 1] + bpre[blockIdx.x];
    rowptr[idx + 1] = val;
    if (idx + 1 < n) cursor[idx + 1] = val;
    if (idx == 0) { rowptr[0] = 0; cursor[0] = 0; }
}

__global__ void k_scatter(const int* __restrict__ src, const int* __restrict__ dst,
                          const float* __restrict__ ew, const float* __restrict__ dinv,
                          int* cursor, int* csrc, float* cw, int E) {
    int e = blockIdx.x * blockDim.x + threadIdx.x;
    if (e >= E) return;
    int s = src[e], d = dst[e];
    int pos = atomicAdd(&cursor[d], 1);
    csrc[pos] = s;
    cw[pos] = dinv[s] * ew[e] * dinv[d];
}

// ---------------- GEMM: O[n,128] = X[n,128] @ W^T (W row-major [j][k]) ----------------
__global__ void __launch_bounds__(256)
k_gemm(const float* __restrict__ X, const float* __restrict__ W,
       float* __restrict__ O, int nrows) {
    extern __shared__ float sm[];
    float* Xs = sm;                  // [128][132] row-major, padded
    float* Ws = sm + 128 * 132;      // [128][132] transposed: Ws[k*132+j]
    int tid = threadIdx.x;
    int tx = tid & 15, ty = tid >> 4;
    int row0 = blockIdx.x * 128;

#pragma unroll
    for (int i = 0; i < 16; i++) {
        int idx = i * 256 + tid;      // 0..4095 (float4 index)
        int r = idx >> 5, k4 = idx & 31;
        int grow = row0 + r;
        float4 v = make_float4(0.f, 0.f, 0.f, 0.f);
        if (grow < nrows) v = ((const float4*)(X + (size_t)grow * HID))[k4];
        *(float4*)(Xs + r * 132 + k4 * 4) = v;
        // W: j = r (row), k = k4*4.. ; store transposed into Ws
        float4 w = ((const float4*)W)[idx];
        Ws[(k4 * 4 + 0) * 132 + r] = w.x;
        Ws[(k4 * 4 + 1) * 132 + r] = w.y;
        Ws[(k4 * 4 + 2) * 132 + r] = w.z;
        Ws[(k4 * 4 + 3) * 132 + r] = w.w;
    }
    __syncthreads();

    float acc[8][8];
#pragma unroll
    for (int i = 0; i < 8; i++)
#pragma unroll
        for (int j = 0; j < 8; j++) acc[i][j] = 0.f;

#pragma unroll 4
    for (int k = 0; k < 128; k++) {
        float a[8];
#pragma unroll
        for (int i = 0; i < 8; i++) a[i] = Xs[(ty * 8 + i) * 132 + k];
        float4 b0 = *(const float4*)(Ws + k * 132 + tx * 8);
        float4 b1 = *(const float4*)(Ws + k * 132 + tx * 8 + 4);
        float b[8] = {b0.x, b0.y, b0.z, b0.w, b1.x, b1.y, b1.z, b1.w};
#pragma unroll
        for (int i = 0; i < 8; i++)
#pragma unroll
            for (int j = 0; j < 8; j++) acc[i][j] += a[i] * b[j];
    }

#pragma unroll
    for (int i = 0; i < 8; i++) {
        int grow = row0 + ty * 8 + i;
        if (grow < nrows) {
            float4 o0 = make_float4(acc[i][0], acc[i][1], acc[i][2], acc[i][3]);
            float4 o1 = make_float4(acc[i][4], acc[i][5], acc[i][6], acc[i][7]);
            *(float4*)(O + (size_t)grow * HID + tx * 8) = o0;
            *(float4*)(O + (size_t)grow * HID + tx * 8 + 4) = o1;
        }
    }
}

// ---------------- CSR gather aggregation, fused self-loop + bias + ReLU ----------------
// one warp per node: out[d] = relu( h[d]*dinv[d]^2 + sum_e c_e * h[src_e] + bias )
__global__ void __launch_bounds__(256)
k_agg_csr(const float* __restrict__ h, const int* __restrict__ rowptr,
          const int* __restrict__ csrc, const float* __restrict__ cw,
          const float* __restrict__ dinv, const float* __restrict__ bias,
          float* __restrict__ out, int n) {
    int gt = blockIdx.x * blockDim.x + threadIdx.x;
    int node = gt >> 5, lane = gt & 31;
    if (node >= n) return;
    const float4* h4 = (const float4*)h;

    float di = dinv[node];
    float c0 = di * di;
    float4 acc = h4[(size_t)node * 32 + lane];
    acc.x *= c0; acc.y *= c0; acc.z *= c0; acc.w *= c0;

    int beg = rowptr[node], end = rowptr[node + 1];
    int i = beg;
    // 2-deep software pipeline over the gather chain
    for (; i + 1 < end; i += 2) {
        int   s0 = csrc[i],     s1 = csrc[i + 1];
        float w0 = cw[i],       w1 = cw[i + 1];
        float4 v0 = h4[(size_t)s0 * 32 + lane];
        float4 v1 = h4[(size_t)s1 * 32 + lane];
        acc.x += w0 * v0.x + w1 * v1.x;
        acc.y += w0 * v0.y + w1 * v1.y;
        acc.z += w0 * v0.z + w1 * v1.z;
        acc.w += w0 * v0.w + w1 * v1.w;
    }
    if (i < end) {
        int s = csrc[i]; float w = cw[i];
        float4 v = h4[(size_t)s * 32 + lane];
        acc.x += w * v.x; acc.y += w * v.y; acc.z += w * v.z; acc.w += w * v.w;
    }

    float4 b = ((const float4*)bias)[lane];
    acc.x = fmaxf(acc.x + b.x, 0.f);
    acc.y = fmaxf(acc.y + b.y, 0.f);
    acc.z = fmaxf(acc.z + b.z, 0.f);
    acc.w = fmaxf(acc.w + b.w, 0.f);
    ((float4*)out)[(size_t)node * 32 + lane] = acc;
}

// ---------------- fused mean-pool + MLP head (batch is sorted) ----------------
__global__ void __launch_bounds__(128)
k_poolmlp(const float* __restrict__ a, const int* __restrict__ batch, int n,
          const float* __restrict__ fW1, const float* __restrict__ fb1,
          const float* __restrict__ fW2, const float* __restrict__ fb2,
          float* __restrict__ out) {
    __shared__ int seg[2];
    __shared__ float p[128];
    __shared__ float z[128];
    int g = blockIdx.x, t = threadIdx.x;

    if (t < 2) {
        // lower_bound for value g+t in sorted batch
        int key = g + t, lo = 0, hi = n;
        while (lo < hi) { int mid = (lo + hi) >> 1; if (batch[mid] < key) lo = mid + 1; else hi = mid; }
        seg[t] = lo;
    }
    __syncthreads();
    int start = seg[0], end = seg[1];

    float acc = 0.f;
    for (int i = start; i < end; i++) acc += a[(size_t)i * HID + t];
    float cnt = fmaxf((float)(end - start), 1.0f);
    p[t] = acc / cnt;
    __syncthreads();

    float s1 = fb1[t];
    const float* wr = fW1 + t * HID;
#pragma unroll 4
    for (int k = 0; k < HID; k++) s1 += p[k] * wr[k];
    z[t] = fmaxf(s1, 0.f) * fW2[t];
    __syncthreads();
    if (t < 32) {
        float s = z[t] + z[t + 32] + z[t + 64] + z[t + 96];
#pragma unroll
        for (int o = 16; o; o >>= 1) s += __shfl_down_sync(0xffffffffu, s, o);
        if (t == 0) out[g] = s + fb2[0];
    }
}

// ---------------- launch ----------------
extern "C" void kernel_launch(void* const* d_in, const int* in_sizes, int n_in,
                              void* d_out, int out_size) {
    const float* x     = (const float*)d_in[0];
    const int*   eidx  = (const int*)d_in[1];
    const float* eattr = (const float*)d_in[2];
    const int*   batch = (const int*)d_in[3];
    const float* W1    = (const float*)d_in[4];
    const float* b1    = (const float*)d_in[5];
    const float* W2    = (const float*)d_in[6];
    const float* b2    = (const float*)d_in[7];
    const float* fW1   = (const float*)d_in[8];
    const float* fb1   = (const float*)d_in[9];
    const float* fW2   = (const float*)d_in[10];
    const float* fb2   = (const float*)d_in[11];
    float* out = (float*)d_out;

    int N = in_sizes[0] / HID;
    int E = in_sizes[1] / 2;
    const int* src = eidx;
    const int* dst = eidx + E;

    float *p_h, *p_t, *p_deg, *p_cw;
    int *p_hist, *p_rowptr, *p_cursor, *p_bsum, *p_bpre, *p_csrc;
    cudaGetSymbolAddress((void**)&p_h, g_h);
    cudaGetSymbolAddress((void**)&p_t, g_t);
    cudaGetSymbolAddress((void**)&p_deg, g_deg);
    cudaGetSymbolAddress((void**)&p_hist, g_hist);
    cudaGetSymbolAddress((void**)&p_rowptr, g_rowptr);
    cudaGetSymbolAddress((void**)&p_cursor, g_cursor);
    cudaGetSymbolAddress((void**)&p_bsum, g_bsum);
    cudaGetSymbolAddress((void**)&p_bpre, g_bpre);
    cudaGetSymbolAddress((void**)&p_csrc, g_csrc);
    cudaGetSymbolAddress((void**)&p_cw, g_cw);

    const int T = 256;
    int gemm_blocks = (N + 127) / 128;
    int agg_blocks = (int)(((long long)N * 32 + T - 1) / T);
    int scan_blocks = (N + 1023) / 1024;
    size_t gemm_smem = (size_t)2 * 128 * 132 * sizeof(float);
    cudaFuncSetAttribute(k_gemm, cudaFuncAttributeMaxDynamicSharedMemorySize,
                         (int)gemm_smem);

    // ---- CSR build + normalization coefficients ----
    k_init_nodes<<<(N + T - 1) / T, T>>>(p_deg, p_hist, N);
    k_edge_hist<<<(E + T - 1) / T, T>>>(dst, eattr, p_deg, p_hist, E);
    k_rsqrt<<<(N + T - 1) / T, T>>>(p_deg, N);           // g_deg now holds dinv
    k_scan1<<<scan_blocks, 1024>>>(p_hist, p_rowptr, p_bsum, N);
    k_scan2<<<1, 32>>>(p_bsum, p_bpre, scan_blocks);
    k_scan3<<<scan_blocks, 1024>>>(p_rowptr, p_cursor, p_bpre, N);
    k_scatter<<<(E + T - 1) / T, T>>>(src, dst, eattr, p_deg, p_cursor, p_csrc, p_cw, E);

    // ---- layer 1 ----
    k_gemm<<<gemm_blocks, T, gemm_smem>>>(x, W1, p_h, N);
    k_agg_csr<<<agg_blocks, T>>>(p_h, p_rowptr, p_csrc, p_cw, p_deg, b1, p_t, N);

    // ---- layer 2 ----
    k_gemm<<<gemm_blocks, T, gemm_smem>>>(p_t, W2, p_h, N);
    k_agg_csr<<<agg_blocks, T>>>(p_h, p_rowptr, p_csrc, p_cw, p_deg, b2, p_t, N);

    // ---- pool + MLP ----
    k_poolmlp<<<NGRAPH, 128>>>(p_t, batch, N, fW1, fb1, fW2, fb2, out);
}